// round 4
// baseline (speedup 1.0000x reference)
#include <cuda_runtime.h>
#include <math.h>

#define FULLMASK 0xFFFFFFFFu

// 2*512*512*128 floats = 256 MiB scratch for the fc1+gelu intermediate "h".
__device__ float g_h[2u * 512u * 512u * 128u];
// dense 64x64 attention bias (bias_table gathered through rel_idx)
__device__ float g_bias[64 * 64];

// ---------------- packed fp32x2 helpers (Blackwell FFMA2) ----------------
__device__ __forceinline__ unsigned long long pk2(float a, float b) {
    unsigned long long r;
    asm("mov.b64 %0, {%1,%2};" : "=l"(r) : "f"(a), "f"(b));
    return r;
}
__device__ __forceinline__ void upk2(unsigned long long v, float& a, float& b) {
    asm("mov.b64 {%0,%1}, %2;" : "=f"(a), "=f"(b) : "l"(v));
}
__device__ __forceinline__ unsigned long long ffma2(unsigned long long a,
                                                    unsigned long long b,
                                                    unsigned long long c) {
    unsigned long long d;
    asm("fma.rn.f32x2 %0, %1, %2, %3;" : "=l"(d) : "l"(a), "l"(b), "l"(c));
    return d;
}

__device__ __forceinline__ float leaky(float z) { return z >= 0.f ? z : 0.3f * z; }

__device__ __forceinline__ float rcp_fast(float x) {
    float r; asm("rcp.approx.f32 %0, %1;" : "=f"(r) : "f"(x)); return r;
}

// branch-free gelu via Abramowitz-Stegun 7.1.26 erf (abs err <= 1.5e-7)
__device__ __forceinline__ float fast_gelu(float x) {
    float u  = x * 0.70710678118654752f;
    float au = fabsf(u);
    float t  = rcp_fast(fmaf(0.3275911f, au, 1.0f));
    float p  = fmaf(1.061405429f, t, -1.453152027f);
    p = fmaf(p, t, 1.421413741f);
    p = fmaf(p, t, -0.284496736f);
    p = fmaf(p, t, 0.254829592f);
    p *= t;
    float e    = __expf(-u * u);
    float erfa = fmaf(-p, e, 1.0f);
    float erfu = copysignf(erfa, u);
    return 0.5f * x * (1.0f + erfu);
}

// ============================================================================
// K0: g_bias[n][m] = bias_table[rel_idx[n*64+m]]   (HEADS = 1)
// ============================================================================
__global__ void k0_bias(const float* __restrict__ bt, const int* __restrict__ ridx) {
    int i = blockIdx.x * 256 + threadIdx.x;   // 16*256 = 4096
    g_bias[i] = bt[ridx[i]];
}

// ============================================================================
// K1: LN1 + window QKV(leaky) + softmax(QK^T*scale + bias) + PV + proj
//     + shortcut residual -> x2 (stored into d_out as scratch)
// ============================================================================
__global__ void __launch_bounds__(256, 2) k1_attn(
    const float* __restrict__ x,
    const float* __restrict__ g1, const float* __restrict__ be1,
    const float* __restrict__ Wq, const float* __restrict__ bq,
    const float* __restrict__ Wkv, const float* __restrict__ bkv,
    const float* __restrict__ Wp, const float* __restrict__ bp,
    float* __restrict__ x2)
{
    extern __shared__ float sm[];
    float* sWq   = sm;              // 1024
    float* sWkv  = sm + 1024;       // 2048
    float* sWp   = sm + 3072;       // 1024
    float* sBias = sm + 4096;       // 64*66 = 4224
    float* sBq   = sm + 8320;       // 32
    float* sBkv  = sm + 8352;       // 64
    float* sBp   = sm + 8416;       // 32
    float* sG1   = sm + 8448;       // 32
    float* sBe1  = sm + 8480;       // 32
    const int tid = threadIdx.x;
    float* winb = sm + 8512 + (tid >> 6) * 4480;
    float* kT   = winb;
    float* sV   = winb + 2176;

    const int t   = tid & 63;
    const int win = blockIdx.x * 4 + (tid >> 6);
    const int b   = win >> 12;
    const int wr  = (win >> 6) & 63;
    const int wc  = win & 63;

    for (int i = tid; i < 1024; i += 256) sWq[i] = Wq[i];
    for (int i = tid; i < 2048; i += 256) sWkv[i] = Wkv[i];
    for (int i = tid; i < 1024; i += 256) sWp[i] = Wp[i];
    for (int i = tid; i < 4096; i += 256) sBias[(i >> 6) * 66 + (i & 63)] = g_bias[i];
    if (tid < 32) { sBq[tid] = bq[tid]; sBp[tid] = bp[tid]; sG1[tid] = g1[tid]; sBe1[tid] = be1[tid]; }
    if (tid < 64) sBkv[tid] = bkv[tid];

    const int py = wr * 8 + (t >> 3);
    const int px = wc * 8 + (t & 7);
    const float* xp = x + ((size_t)b * 262144u + (size_t)py * 512u + px) * 32u;
    float xv[32];
    #pragma unroll
    for (int j = 0; j < 8; j++) {
        float4 v = ((const float4*)xp)[j];
        xv[4 * j] = v.x; xv[4 * j + 1] = v.y; xv[4 * j + 2] = v.z; xv[4 * j + 3] = v.w;
    }
    float s = 0.f;
    #pragma unroll
    for (int c = 0; c < 32; c++) s += xv[c];
    float m = s * (1.f / 32.f);
    float vs = 0.f;
    #pragma unroll
    for (int c = 0; c < 32; c++) { float d = xv[c] - m; vs += d * d; }
    float inv = rsqrtf(vs * (1.f / 32.f) + 1e-3f);

    __syncthreads();

    float xn[32];
    #pragma unroll
    for (int c = 0; c < 32; c++) xn[c] = (xv[c] - m) * inv * sG1[c] + sBe1[c];

    // K -> kT[d][t]
    {
        unsigned long long a[16];
        #pragma unroll
        for (int i = 0; i < 16; i++) a[i] = pk2(sBkv[2 * i], sBkv[2 * i + 1]);
        #pragma unroll
        for (int c = 0; c < 32; c++) {
            unsigned long long xc = pk2(xn[c], xn[c]);
            const ulonglong2* wrow = (const ulonglong2*)(sWkv + c * 64);
            #pragma unroll
            for (int j = 0; j < 8; j++) {
                ulonglong2 wv = wrow[j];
                a[2 * j]     = ffma2(xc, wv.x, a[2 * j]);
                a[2 * j + 1] = ffma2(xc, wv.y, a[2 * j + 1]);
            }
        }
        #pragma unroll
        for (int i = 0; i < 16; i++) {
            float f0, f1; upk2(a[i], f0, f1);
            kT[(2 * i) * 68 + t]     = leaky(f0);
            kT[(2 * i + 1) * 68 + t] = leaky(f1);
        }
    }
    // V -> sV[t][d]
    {
        unsigned long long a[16];
        #pragma unroll
        for (int i = 0; i < 16; i++) a[i] = pk2(sBkv[32 + 2 * i], sBkv[32 + 2 * i + 1]);
        #pragma unroll
        for (int c = 0; c < 32; c++) {
            unsigned long long xc = pk2(xn[c], xn[c]);
            const ulonglong2* wrow = (const ulonglong2*)(sWkv + c * 64 + 32);
            #pragma unroll
            for (int j = 0; j < 8; j++) {
                ulonglong2 wv = wrow[j];
                a[2 * j]     = ffma2(xc, wv.x, a[2 * j]);
                a[2 * j + 1] = ffma2(xc, wv.y, a[2 * j + 1]);
            }
        }
        float4* vrow = (float4*)(sV + t * 36);
        #pragma unroll
        for (int j = 0; j < 8; j++) {
            float f0, f1, f2, f3;
            upk2(a[2 * j], f0, f1); upk2(a[2 * j + 1], f2, f3);
            float4 o; o.x = leaky(f0); o.y = leaky(f1); o.z = leaky(f2); o.w = leaky(f3);
            vrow[j] = o;
        }
    }
    // Q (registers)
    float q[32];
    {
        unsigned long long a[16];
        #pragma unroll
        for (int i = 0; i < 16; i++) a[i] = pk2(sBq[2 * i], sBq[2 * i + 1]);
        #pragma unroll
        for (int c = 0; c < 32; c++) {
            unsigned long long xc = pk2(xn[c], xn[c]);
            const ulonglong2* wrow = (const ulonglong2*)(sWq + c * 32);
            #pragma unroll
            for (int j = 0; j < 8; j++) {
                ulonglong2 wv = wrow[j];
                a[2 * j]     = ffma2(xc, wv.x, a[2 * j]);
                a[2 * j + 1] = ffma2(xc, wv.y, a[2 * j + 1]);
            }
        }
        #pragma unroll
        for (int i = 0; i < 16; i++) {
            float f0, f1; upk2(a[i], f0, f1);
            q[2 * i]     = leaky(f0) * 0.17677669529663687f;
            q[2 * i + 1] = leaky(f1) * 0.17677669529663687f;
        }
    }
    __syncthreads();

    // scores
    unsigned long long accs[32];
    {
        const float2* brow = (const float2*)(sBias + t * 66);
        #pragma unroll
        for (int i = 0; i < 32; i++) { float2 bb = brow[i]; accs[i] = pk2(bb.x, bb.y); }
        #pragma unroll
        for (int d = 0; d < 32; d++) {
            unsigned long long qd = pk2(q[d], q[d]);
            const ulonglong2* kr = (const ulonglong2*)(kT + d * 68);
            #pragma unroll
            for (int j = 0; j < 16; j++) {
                ulonglong2 kk = kr[j];
                accs[2 * j]     = ffma2(qd, kk.x, accs[2 * j]);
                accs[2 * j + 1] = ffma2(qd, kk.y, accs[2 * j + 1]);
            }
        }
    }
    // softmax
    float pinv;
    {
        float mx = -1e30f;
        #pragma unroll
        for (int i = 0; i < 32; i++) { float a0, a1; upk2(accs[i], a0, a1); mx = fmaxf(mx, fmaxf(a0, a1)); }
        float sum = 0.f;
        #pragma unroll
        for (int i = 0; i < 32; i++) {
            float a0, a1; upk2(accs[i], a0, a1);
            float e0 = __expf(a0 - mx), e1 = __expf(a1 - mx);
            sum += e0 + e1;
            accs[i] = pk2(e0, e1);
        }
        pinv = 1.f / sum;
    }
    // P @ V
    unsigned long long outp[16];
    {
        unsigned long long z = pk2(0.f, 0.f);
        #pragma unroll
        for (int i = 0; i < 16; i++) outp[i] = z;
        #pragma unroll
        for (int i = 0; i < 32; i++) {
            float p0, p1; upk2(accs[i], p0, p1);
            p0 *= pinv; p1 *= pinv;
            unsigned long long pm0 = pk2(p0, p0);
            const ulonglong2* vr0 = (const ulonglong2*)(sV + (2 * i) * 36);
            #pragma unroll
            for (int j = 0; j < 8; j++) {
                ulonglong2 vv = vr0[j];
                outp[2 * j]     = ffma2(pm0, vv.x, outp[2 * j]);
                outp[2 * j + 1] = ffma2(pm0, vv.y, outp[2 * j + 1]);
            }
            unsigned long long pm1 = pk2(p1, p1);
            const ulonglong2* vr1 = (const ulonglong2*)(sV + (2 * i + 1) * 36);
            #pragma unroll
            for (int j = 0; j < 8; j++) {
                ulonglong2 vv = vr1[j];
                outp[2 * j]     = ffma2(pm1, vv.x, outp[2 * j]);
                outp[2 * j + 1] = ffma2(pm1, vv.y, outp[2 * j + 1]);
            }
        }
    }
    // proj
    unsigned long long accf[16];
    {
        #pragma unroll
        for (int i = 0; i < 16; i++) accf[i] = pk2(sBp[2 * i], sBp[2 * i + 1]);
        #pragma unroll
        for (int i = 0; i < 16; i++) {
            float o0, o1; upk2(outp[i], o0, o1);
            unsigned long long m0 = pk2(o0, o0);
            const ulonglong2* wr0 = (const ulonglong2*)(sWp + (2 * i) * 32);
            #pragma unroll
            for (int j = 0; j < 8; j++) {
                ulonglong2 wv = wr0[j];
                accf[2 * j]     = ffma2(m0, wv.x, accf[2 * j]);
                accf[2 * j + 1] = ffma2(m0, wv.y, accf[2 * j + 1]);
            }
            unsigned long long m1 = pk2(o1, o1);
            const ulonglong2* wr1 = (const ulonglong2*)(sWp + (2 * i + 1) * 32);
            #pragma unroll
            for (int j = 0; j < 8; j++) {
                ulonglong2 wv = wr1[j];
                accf[2 * j]     = ffma2(m1, wv.x, accf[2 * j]);
                accf[2 * j + 1] = ffma2(m1, wv.y, accf[2 * j + 1]);
            }
        }
    }
    // x2 = shortcut + proj
    {
        float* op = x2 + ((size_t)b * 262144u + (size_t)py * 512u + px) * 32u;
        #pragma unroll
        for (int j = 0; j < 8; j++) {
            float4 sc = ((const float4*)xp)[j];
            float f0, f1, f2, f3;
            upk2(accf[2 * j], f0, f1); upk2(accf[2 * j + 1], f2, f3);
            float4 o; o.x = sc.x + f0; o.y = sc.y + f1; o.z = sc.z + f2; o.w = sc.w + f3;
            ((float4*)op)[j] = o;
        }
    }
}

// ============================================================================
// K2: h = gelu( LN2(x2) @ W1 + b1 )  -> g_h
// 4096 blocks x 256 thr, 128 tokens/block. Register-tiled GEMM:
// thread tile = 8 tok x 8 ch, tok-pairs packed f32x2, W pre-duplicated.
// ============================================================================
__global__ void __launch_bounds__(256, 2) k2_ff1(
    const float* __restrict__ x2,
    const float* __restrict__ g2, const float* __restrict__ be2,
    const float* __restrict__ W1, const float* __restrict__ b1)
{
    extern __shared__ float sm2[];
    float* sXnT = sm2;                                   // 32*132 = 4224 floats
    unsigned long long* sW1d = (unsigned long long*)(sm2 + 4224); // 4096 ull = 32KB
    float* sB1 = (float*)(sW1d + 4096);                  // 128

    const int tid = threadIdx.x;
    const int lane = tid & 31, w = tid >> 5;

    for (int i = tid; i < 4096; i += 256) { float v = W1[i]; sW1d[i] = pk2(v, v); }
    if (tid < 128) sB1[tid] = b1[tid];

    const float gml = __ldg(g2 + lane), bel = __ldg(be2 + lane);
    const size_t tok0 = (size_t)blockIdx.x * 128;

    // LN: warp w handles tokens w*16 .. w*16+15 -> sXnT[c][t] transposed
    #pragma unroll 1
    for (int i = 0; i < 16; i++) {
        int t = w * 16 + i;
        float xvv = x2[(tok0 + t) * 32 + lane];
        float s = xvv;
        #pragma unroll
        for (int o = 16; o; o >>= 1) s += __shfl_xor_sync(FULLMASK, s, o);
        float mm = s * (1.f / 32.f);
        float dd = xvv - mm;
        float vsq = dd * dd;
        #pragma unroll
        for (int o = 16; o; o >>= 1) vsq += __shfl_xor_sync(FULLMASK, vsq, o);
        sXnT[lane * 132 + t] = dd * rsqrtf(vsq * (1.f / 32.f) + 1e-3f) * gml + bel;
    }
    __syncthreads();

    // GEMM: 128 tok x 128 ch, K=32. Thread: 8 tok x 8 ch.
    const int ch8 = (tid & 15) * 8;
    const int t8  = (tid >> 4) * 8;

    unsigned long long acc[4][8];
    #pragma unroll
    for (int k = 0; k < 8; k++) {
        unsigned long long bb = pk2(sB1[ch8 + k], sB1[ch8 + k]);
        acc[0][k] = bb; acc[1][k] = bb; acc[2][k] = bb; acc[3][k] = bb;
    }
    #pragma unroll 4
    for (int c = 0; c < 32; c++) {
        ulonglong2 A0 = *(const ulonglong2*)(sXnT + c * 132 + t8);
        ulonglong2 A1 = *(const ulonglong2*)(sXnT + c * 132 + t8 + 4);
        ulonglong2 Wd0 = *(const ulonglong2*)(sW1d + c * 128 + ch8);
        ulonglong2 Wd1 = *(const ulonglong2*)(sW1d + c * 128 + ch8 + 2);
        ulonglong2 Wd2 = *(const ulonglong2*)(sW1d + c * 128 + ch8 + 4);
        ulonglong2 Wd3 = *(const ulonglong2*)(sW1d + c * 128 + ch8 + 6);
        unsigned long long wv[8] = {Wd0.x, Wd0.y, Wd1.x, Wd1.y, Wd2.x, Wd2.y, Wd3.x, Wd3.y};
        unsigned long long ap[4] = {A0.x, A0.y, A1.x, A1.y};
        #pragma unroll
        for (int p = 0; p < 4; p++)
            #pragma unroll
            for (int k = 0; k < 8; k++)
                acc[p][k] = ffma2(ap[p], wv[k], acc[p][k]);
    }
    // epilogue: gelu + store
    #pragma unroll
    for (int p = 0; p < 4; p++) {
        float ev[8], ov[8];
        #pragma unroll
        for (int k = 0; k < 8; k++) upk2(acc[p][k], ev[k], ov[k]);
        size_t tokA = tok0 + t8 + 2 * p;
        float4 f0, f1;
        f0.x = fast_gelu(ev[0]); f0.y = fast_gelu(ev[1]); f0.z = fast_gelu(ev[2]); f0.w = fast_gelu(ev[3]);
        f1.x = fast_gelu(ev[4]); f1.y = fast_gelu(ev[5]); f1.z = fast_gelu(ev[6]); f1.w = fast_gelu(ev[7]);
        *(float4*)(g_h + tokA * 128 + ch8)     = f0;
        *(float4*)(g_h + tokA * 128 + ch8 + 4) = f1;
        f0.x = fast_gelu(ov[0]); f0.y = fast_gelu(ov[1]); f0.z = fast_gelu(ov[2]); f0.w = fast_gelu(ov[3]);
        f1.x = fast_gelu(ov[4]); f1.y = fast_gelu(ov[5]); f1.z = fast_gelu(ov[6]); f1.w = fast_gelu(ov[7]);
        *(float4*)(g_h + (tokA + 1) * 128 + ch8)     = f0;
        *(float4*)(g_h + (tokA + 1) * 128 + ch8 + 4) = f1;
    }
}

// ============================================================================
// K3: depthwise 3x3 (direct gmem reads through L1, sliding row window)
//     + gelu -> h'T (transposed smem) -> fc2 register-tiled f32x2 -> out += mlp
// 16x8 pixel tile per block; grid (64, 32, 2).
// ============================================================================
__global__ void __launch_bounds__(256, 2) k3_conv_ff2(
    const float* __restrict__ dwk, const float* __restrict__ dwb,
    const float* __restrict__ W2, const float* __restrict__ b2,
    float* __restrict__ out)
{
    extern __shared__ float sm3[];
    unsigned long long* sW2d = (unsigned long long*)sm3;   // 4096 ull = 32KB
    float* sHpT = sm3 + 8192;                              // 128*132 = 16896 floats

    const int tid = threadIdx.x;
    const int lane = tid & 31, w = tid >> 5;
    const int bxx = blockIdx.x, byy = blockIdx.y, bz = blockIdx.z;
    const int x0 = bxx * 8, y0 = byy * 16;

    for (int i = tid; i < 4096; i += 256) { float v = W2[i]; sW2d[i] = pk2(v, v); }

    // ---- depthwise conv + gelu (rows rg..rg+7, channel ch) ----
    {
        const int ch = (w & 3) * 32 + lane;
        const int rg = (w >> 2) * 8;
        float kw[9];
        #pragma unroll
        for (int q9 = 0; q9 < 9; q9++) kw[q9] = __ldg(dwk + q9 * 128 + ch);
        const float db = __ldg(dwb + ch);
        const float* hb = g_h + (size_t)bz * (512u * 512u * 128u) + ch;

        float R[3][10];
        // preload rows y0+rg-1 (buf 0) and y0+rg (buf 1)
        #pragma unroll
        for (int bufi = 0; bufi < 2; bufi++) {
            int pyr = y0 + rg - 1 + bufi;
            bool okY = (pyr >= 0) && (pyr < 512);
            #pragma unroll
            for (int xx = 0; xx < 10; xx++) {
                int hx = x0 - 1 + xx;
                bool ok = okY && (hx >= 0) && (hx < 512);
                R[bufi][xx] = ok ? hb[((size_t)pyr * 512 + hx) * 128u] : 0.f;
            }
        }
        #pragma unroll
        for (int r = 0; r < 8; r++) {
            // load next row into buf (r+2)%3
            {
                int pyr = y0 + rg + r + 1;
                bool okY = (pyr < 512);
                #pragma unroll
                for (int xx = 0; xx < 10; xx++) {
                    int hx = x0 - 1 + xx;
                    bool ok = okY && (hx >= 0) && (hx < 512);
                    R[(r + 2) % 3][xx] = ok ? hb[((size_t)pyr * 512 + hx) * 128u] : 0.f;
                }
            }
            const float* Ar = R[r % 3];
            const float* Br = R[(r + 1) % 3];
            const float* Cr = R[(r + 2) % 3];
            float* dst = sHpT + ch * 132 + (rg + r) * 8;
            #pragma unroll
            for (int pxl = 0; pxl < 8; pxl++) {
                float acc = db;
                acc = fmaf(Ar[pxl], kw[0], acc);
                acc = fmaf(Ar[pxl + 1], kw[1], acc);
                acc = fmaf(Ar[pxl + 2], kw[2], acc);
                acc = fmaf(Br[pxl], kw[3], acc);
                acc = fmaf(Br[pxl + 1], kw[4], acc);
                acc = fmaf(Br[pxl + 2], kw[5], acc);
                acc = fmaf(Cr[pxl], kw[6], acc);
                acc = fmaf(Cr[pxl + 1], kw[7], acc);
                acc = fmaf(Cr[pxl + 2], kw[8], acc);
                dst[pxl] = fast_gelu(acc);
            }
        }
    }
    __syncthreads();

    // ---- fc2: 128 tok x 32 ch, K=128. Thread: 4 tok x 4 ch (tok-pairs packed) ----
    {
        const int ch4 = (tid & 7) * 4;
        const int t4  = (tid >> 3) * 4;
        unsigned long long acc2[2][4];
        #pragma unroll
        for (int c = 0; c < 4; c++) {
            float bv = __ldg(b2 + ch4 + c);
            unsigned long long bb = pk2(bv, bv);
            acc2[0][c] = bb; acc2[1][c] = bb;
        }
        #pragma unroll 8
        for (int cin = 0; cin < 128; cin++) {
            ulonglong2 A   = *(const ulonglong2*)(sHpT + cin * 132 + t4);
            ulonglong2 W01 = *(const ulonglong2*)(sW2d + cin * 32 + ch4);
            ulonglong2 W23 = *(const ulonglong2*)(sW2d + cin * 32 + ch4 + 2);
            acc2[0][0] = ffma2(A.x, W01.x, acc2[0][0]);
            acc2[0][1] = ffma2(A.x, W01.y, acc2[0][1]);
            acc2[0][2] = ffma2(A.x, W23.x, acc2[0][2]);
            acc2[0][3] = ffma2(A.x, W23.y, acc2[0][3]);
            acc2[1][0] = ffma2(A.y, W01.x, acc2[1][0]);
            acc2[1][1] = ffma2(A.y, W01.y, acc2[1][1]);
            acc2[1][2] = ffma2(A.y, W23.x, acc2[1][2]);
            acc2[1][3] = ffma2(A.y, W23.y, acc2[1][3]);
        }
        #pragma unroll
        for (int p = 0; p < 2; p++) {
            float ev[4], ov[4];
            #pragma unroll
            for (int c = 0; c < 4; c++) upk2(acc2[p][c], ev[c], ov[c]);
            int tokA = t4 + 2 * p;
            int ry = tokA >> 3, rx = tokA & 7;
            size_t gA = ((size_t)(bz * 512 + y0 + ry) * 512 + (x0 + rx)) * 32u + ch4;
            float4 oldA = *(const float4*)(out + gA);
            float4 nA; nA.x = oldA.x + ev[0]; nA.y = oldA.y + ev[1]; nA.z = oldA.z + ev[2]; nA.w = oldA.w + ev[3];
            *(float4*)(out + gA) = nA;
            int tokB = tokA + 1;
            int ry2 = tokB >> 3, rx2 = tokB & 7;
            size_t gB = ((size_t)(bz * 512 + y0 + ry2) * 512 + (x0 + rx2)) * 32u + ch4;
            float4 oldB = *(const float4*)(out + gB);
            float4 nB; nB.x = oldB.x + ov[0]; nB.y = oldB.y + ov[1]; nB.z = oldB.z + ov[2]; nB.w = oldB.w + ov[3];
            *(float4*)(out + gB) = nB;
        }
    }
}

// ============================================================================
// launch
// ============================================================================
extern "C" void kernel_launch(void* const* d_in, const int* in_sizes, int n_in,
                              void* d_out, int out_size)
{
    const float* x          = (const float*)d_in[0];
    const float* g1         = (const float*)d_in[1];
    const float* beta1      = (const float*)d_in[2];
    const float* Wq         = (const float*)d_in[3];
    const float* bq         = (const float*)d_in[4];
    const float* Wkv        = (const float*)d_in[5];
    const float* bkv        = (const float*)d_in[6];
    const float* bias_table = (const float*)d_in[7];
    const float* Wp         = (const float*)d_in[8];
    const float* bp         = (const float*)d_in[9];
    const float* g2         = (const float*)d_in[10];
    const float* beta2      = (const float*)d_in[11];
    const float* W1         = (const float*)d_in[12];
    const float* b1m        = (const float*)d_in[13];
    const float* dw_k       = (const float*)d_in[14];
    const float* dw_b       = (const float*)d_in[15];
    const float* W2         = (const float*)d_in[16];
    const float* b2m        = (const float*)d_in[17];
    const int*   rel_idx    = (const int*)d_in[18];
    float* out = (float*)d_out;

    const int SMEM1 = 26432 * 4;                    // 105728 B
    const int SMEM2 = 4224 * 4 + 4096 * 8 + 512;    // 50176 B
    const int SMEM3 = 4096 * 8 + 16896 * 4;         // 100352 B
    cudaFuncSetAttribute(k1_attn,     cudaFuncAttributeMaxDynamicSharedMemorySize, SMEM1);
    cudaFuncSetAttribute(k2_ff1,      cudaFuncAttributeMaxDynamicSharedMemorySize, SMEM2);
    cudaFuncSetAttribute(k3_conv_ff2, cudaFuncAttributeMaxDynamicSharedMemorySize, SMEM3);

    k0_bias<<<16, 256>>>(bias_table, rel_idx);
    k1_attn<<<2048, 256, SMEM1>>>(x, g1, beta1, Wq, bq, Wkv, bkv, Wp, bp, out);
    // 4096 blocks * 128 tokens = 524288 tokens  (R3 bug: was 1024)
    k2_ff1<<<4096, 256, SMEM2>>>(out, g2, beta2, W1, b1m);
    k3_conv_ff2<<<dim3(64, 32, 2), 256, SMEM3>>>(dw_k, dw_b, W2, b2m, out);
}